// round 4
// baseline (speedup 1.0000x reference)
#include <cuda_runtime.h>
#include <math.h>

#define DD   2048
#define HH   8
#define KVH  2
#define HDIM 256
#define SS   4096
#define FFD  8192
#define PLD  256
#define LL   8
#define POSI 2048
#define EPSF 1e-6f
#define NSPL 32
#define CHNK 65   // 32*65 = 2080 >= 2049 positions

// ---------------- scratch (device globals; no allocation allowed) ----------------
__device__ float g_h[DD];
__device__ float g_hn[DD];
__device__ float g_qkv[HH*HDIM + 2*KVH*HDIM];   // 3072
__device__ float g_q[HH*HDIM];
__device__ float g_attn[HH*HDIM];
__device__ float g_ff[FFD];
__device__ float g_vec[DD];
__device__ float g_pl[PLD];
__device__ float g_part[HH * NSPL * (HDIM + 2)];
__device__ unsigned g_cnt[8];        // generic self-resetting tickets
__device__ unsigned g_cnt_attn[HH];  // per-head tickets

__device__ __forceinline__ float gelu_tanh(float x) {
    const float c = 0.7978845608028654f;
    return 0.5f * x * (1.0f + tanhf(c * (x + 0.044715f * x * x * x)));
}

__device__ __forceinline__ float warp_sum(float v) {
#pragma unroll
    for (int o = 16; o; o >>= 1) v += __shfl_xor_sync(0xffffffffu, v, o);
    return v;
}

__device__ __forceinline__ float block_sum_256(float v, float* red) {
    int t = threadIdx.x;
    red[t] = v; __syncthreads();
    for (int s = 128; s > 0; s >>= 1) { if (t < s) red[t] += red[t + s]; __syncthreads(); }
    float r = red[0];
    __syncthreads();
    return r;
}

__device__ __forceinline__ float block_max_256(float v, float* red) {
    int t = threadIdx.x;
    red[t] = v; __syncthreads();
    for (int s = 128; s > 0; s >>= 1) { if (t < s) red[t] = fmaxf(red[t], red[t + s]); __syncthreads(); }
    float r = red[0];
    __syncthreads();
    return r;
}

// Correctly-ordered last-block ticket:
// all threads: store results -> __threadfence() -> __syncthreads() -> t0 atomic -> sync
// Consumer side gets an extra fence after winning.
__device__ __forceinline__ bool last_block_ticket(unsigned* cnt, unsigned total) {
    __threadfence();
    __syncthreads();
    __shared__ unsigned isLast;
    if (threadIdx.x == 0) isLast = (atomicInc(cnt, total - 1) == total - 1);
    __syncthreads();
    if (!isLast) return false;
    __threadfence();   // acquire-side: make other blocks' fenced stores visible
    return true;
}

// ---------------- KV cache bulk copy (SM copy; one node) ----------------
__global__ void __launch_bounds__(256) copy_kv_kernel(
        const float4* __restrict__ Ki, const float4* __restrict__ Vi,
        float4* __restrict__ Ko, float4* __restrict__ Vo, int n4) {
    int stride = gridDim.x * blockDim.x;
    for (int i = blockIdx.x * blockDim.x + threadIdx.x; i < n4; i += stride) {
        Ko[i] = Ki[i];
        Vo[i] = Vi[i];
    }
}

// ---------------- h = hidden (copy) ; hn = rms(h) * w ----------------
__global__ void norm0_kernel(const float* __restrict__ hidden, const float* __restrict__ w,
                             float* __restrict__ h, float* __restrict__ hn) {
    __shared__ float red[256];
    int t = threadIdx.x;
    float hv[8]; float ss = 0.f;
#pragma unroll
    for (int j = 0; j < 8; j++) { hv[j] = hidden[t + j * 256]; ss += hv[j] * hv[j]; }
    ss = block_sum_256(ss, red);
    float r = rsqrtf(ss / (float)DD + EPSF);
#pragma unroll
    for (int j = 0; j < 8; j++) { int i = t + j * 256; h[i] = hv[j]; hn[i] = hv[j] * r * w[i]; }
}

// ---------------- fused QKV GEMV + (last block) per-head RMS/scale/RoPE/cache-write ----------
__global__ void __launch_bounds__(256) gemv_qkv_kernel(
        const float* __restrict__ Wq, const float* __restrict__ Wk, const float* __restrict__ Wv,
        const float* __restrict__ x, float* __restrict__ y,
        const float* __restrict__ qn, const float* __restrict__ kn,
        const float* __restrict__ cosv, const float* __restrict__ sinv,
        float* __restrict__ q_out, float* __restrict__ Kpos, float* __restrict__ Vpos,
        unsigned* __restrict__ cnt) {
    __shared__ float4 sx4[DD / 4];
    const float4* x4 = (const float4*)x;
    for (int i = threadIdx.x; i < DD / 4; i += 256) sx4[i] = x4[i];
    __syncthreads();
    int row = blockIdx.x * 8 + (threadIdx.x >> 5);
    int lane = threadIdx.x & 31;
    const float* W; int r;
    if (row < 2048)      { W = Wq; r = row; }
    else if (row < 2560) { W = Wk; r = row - 2048; }
    else                 { W = Wv; r = row - 2560; }
    const float4* Wr = (const float4*)(W + (size_t)r * DD);
    float acc = 0.f;
#pragma unroll 4
    for (int i = lane; i < DD / 4; i += 32) {
        float4 w = Wr[i]; float4 v = sx4[i];
        acc = fmaf(w.x, v.x, acc); acc = fmaf(w.y, v.y, acc);
        acc = fmaf(w.z, v.z, acc); acc = fmaf(w.w, v.w, acc);
    }
    acc = warp_sum(acc);
    if (lane == 0) y[row] = acc;

    if (!last_block_ticket(cnt, gridDim.x)) return;

    // ---- last-block epilogue: per-head rms + scale + rope + cache write ----
    int warp = threadIdx.x >> 5;
    for (int u = warp; u < 12; u += 8) {
        const float* src; const float* nw = nullptr; int rope = 1;
        if (u < 8)        { src = y + u * HDIM; nw = qn; }
        else if (u < 10)  { src = y + HH * HDIM + (u - 8) * HDIM; nw = kn; }
        else              { src = y + HH * HDIM + KVH * HDIM + (u - 10) * HDIM; rope = 0; }
        float v8[8]; float ss = 0.f;
#pragma unroll
        for (int j = 0; j < 8; j++) { v8[j] = src[lane * 8 + j]; ss += v8[j] * v8[j]; }
        ss = warp_sum(ss);
        float rr = rsqrtf(ss / (float)HDIM + EPSF);
#pragma unroll
        for (int j = 0; j < 8; j++) {
            int d = lane * 8 + j;
            float val = v8[j] * rr;
            if (nw) val *= nw[d];
            if (rope) {
                int p = (d < 128) ? d + 128 : d - 128;
                float pv = src[p] * rr * (nw ? nw[p] : 1.f);
                float rot = (d < 128) ? -pv : pv;
                val = val * cosv[d] + rot * sinv[d];
            }
            if (u < 8)       q_out[u * HDIM + d] = val;
            else if (u < 10) Kpos[(size_t)(u - 8) * SS * HDIM + d] = val;
            else             Vpos[(size_t)(u - 10) * SS * HDIM + d] = val;
        }
    }
}

// ---------------- attention: per-(chunk, head) block; 3-phase; last block combines -----------
__global__ void __launch_bounds__(256) attn_part_kernel(
        const float* __restrict__ q, const float* __restrict__ Kl, const float* __restrict__ Vl,
        float* __restrict__ part, float* __restrict__ out) {
    int h = blockIdx.x & 7;
    int chunk = blockIdx.x >> 3;
    int kv = h >> 2;  // N_REP = 4
    const float* Kh = Kl + (size_t)kv * SS * HDIM;
    const float* Vh = Vl + (size_t)kv * SS * HDIM;
    int t = threadIdx.x;
    int warp = t >> 5, lane = t & 31;
    int s0 = chunk * CHNK;
    int n = min(CHNK, POSI + 1 - s0);

    __shared__ float sq[HDIM];
    __shared__ float sc[CHNK];
    __shared__ float red[256];
    sq[t] = q[h * HDIM + t];
    __syncthreads();
    float qa[4], qb[4];
#pragma unroll
    for (int j = 0; j < 4; j++) { qa[j] = sq[lane * 4 + j]; qb[j] = sq[128 + lane * 4 + j]; }

    // Phase A: independent scores
    for (int idx = warp; idx < n; idx += 8) {
        const float* Kr = Kh + (size_t)(s0 + idx) * HDIM;
        float4 ka = *(const float4*)(Kr + lane * 4);
        float4 kb = *(const float4*)(Kr + 128 + lane * 4);
        float d = ka.x * qa[0] + ka.y * qa[1] + ka.z * qa[2] + ka.w * qa[3]
                + kb.x * qb[0] + kb.y * qb[1] + kb.z * qb[2] + kb.w * qb[3];
        d = warp_sum(d);
        if (lane == 0) sc[idx] = d;
    }
    __syncthreads();

    // Phase B: block softmax (unnormalized)
    float v = (t < n) ? sc[t] : -1e30f;
    __syncthreads();
    float M = block_max_256(v, red);
    float e = (t < n) ? expf(v - M) : 0.f;
    float L = block_sum_256(e, red);
    if (t < n) sc[t] = e;
    __syncthreads();

    // Phase C: coalesced V accumulation (thread = dim)
    float acc = 0.f;
#pragma unroll 4
    for (int idx = 0; idx < n; idx++)
        acc = fmaf(sc[idx], Vh[(size_t)(s0 + idx) * HDIM + t], acc);

    float* pp = part + (size_t)(h * NSPL + chunk) * (HDIM + 2);
    pp[t] = acc;
    if (t == 0) { pp[HDIM] = M; pp[HDIM + 1] = L; }

    // ---- last block for this head: combine ----
    if (!last_block_ticket(&g_cnt_attn[h], NSPL)) return;
    __shared__ float cm[NSPL], cl[NSPL];
    if (t < NSPL) {
        const float* cp = part + (size_t)(h * NSPL + t) * (HDIM + 2);
        cm[t] = cp[HDIM]; cl[t] = cp[HDIM + 1];
    }
    __syncthreads();
    float Mg = -1e30f;
#pragma unroll
    for (int c = 0; c < NSPL; c++) Mg = fmaxf(Mg, cm[c]);
    float Lg = 0.f, num = 0.f;
#pragma unroll
    for (int c = 0; c < NSPL; c++) {
        float f = expf(cm[c] - Mg);
        Lg += cl[c] * f;
        num = fmaf(part[(size_t)(h * NSPL + c) * (HDIM + 2) + t], f, num);
    }
    out[h * HDIM + t] = num / Lg;
}

// ---------------- generic GEMV, 256 thr / 8 rows per block, optional fused epilogue --------
// MODE 0: y[row] = Wx
// MODE 1: y[row] = gelu(Wx) * aux[row]
// MODE 2: + last block: h += rms(y)*w1 ; if (w2) hn = rms(h)*w2
// MODE 3: + last block: h = (h + rms(y)*w1)*sc ; if (w2) hn = rms(h)*w2 ; if (out2) out2 = h
template<int COLS, int MODE>
__global__ void __launch_bounds__(256) gemv_kernel(
        const float* __restrict__ W, const float* __restrict__ x, float* __restrict__ y,
        const float* __restrict__ aux,
        const float* __restrict__ w1, float* __restrict__ h,
        const float* __restrict__ w2, float* __restrict__ hn,
        const float* __restrict__ scp, float* __restrict__ out2,
        unsigned* __restrict__ cnt) {
    __shared__ float4 sx4[COLS / 4];
    const float4* x4 = (const float4*)x;
    for (int i = threadIdx.x; i < COLS / 4; i += 256) sx4[i] = x4[i];
    __syncthreads();
    int row = blockIdx.x * 8 + (threadIdx.x >> 5);
    int lane = threadIdx.x & 31;
    const float4* Wr = (const float4*)(W + (size_t)row * COLS);
    float acc = 0.f;
#pragma unroll 4
    for (int i = lane; i < COLS / 4; i += 32) {
        float4 w = Wr[i]; float4 v = sx4[i];
        acc = fmaf(w.x, v.x, acc); acc = fmaf(w.y, v.y, acc);
        acc = fmaf(w.z, v.z, acc); acc = fmaf(w.w, v.w, acc);
    }
    acc = warp_sum(acc);
    if (lane == 0) {
        if (MODE == 1) acc = gelu_tanh(acc) * aux[row];
        y[row] = acc;
    }
    if (MODE < 2) return;

    if (!last_block_ticket(cnt, gridDim.x)) return;

    __shared__ float red[256];
    int t = threadIdx.x;
    float vv[8], hv[8]; float ss = 0.f;
#pragma unroll
    for (int j = 0; j < 8; j++) { int i = t + j * 256; vv[j] = y[i]; ss += vv[j] * vv[j]; }
    ss = block_sum_256(ss, red);
    float r1 = rsqrtf(ss / (float)DD + EPSF);
    float sc = (MODE == 3) ? scp[0] : 1.f;
    float ss2 = 0.f;
#pragma unroll
    for (int j = 0; j < 8; j++) {
        int i = t + j * 256;
        float nh = h[i] + vv[j] * r1 * w1[i];
        if (MODE == 3) nh *= sc;
        hv[j] = nh;
        h[i] = nh;
        if (MODE == 3 && out2) out2[i] = nh;
        ss2 += nh * nh;
    }
    if (w2) {
        ss2 = block_sum_256(ss2, red);
        float r2 = rsqrtf(ss2 / (float)DD + EPSF);
#pragma unroll
        for (int j = 0; j < 8; j++) { int i = t + j * 256; hn[i] = hv[j] * r2 * w2[i]; }
    }
}

// ---------------- fused gated MLP GEMV: y = gelu(Wg x) * (Wu x) ----------------
__global__ void __launch_bounds__(256) gemv_gated_kernel(
        const float* __restrict__ Wg, const float* __restrict__ Wu,
        const float* __restrict__ x, float* __restrict__ y) {
    __shared__ float4 sx4[DD / 4];
    const float4* x4 = (const float4*)x;
    for (int i = threadIdx.x; i < DD / 4; i += 256) sx4[i] = x4[i];
    __syncthreads();
    int row = blockIdx.x * 8 + (threadIdx.x >> 5);
    int lane = threadIdx.x & 31;
    const float4* Wgr = (const float4*)(Wg + (size_t)row * DD);
    const float4* Wur = (const float4*)(Wu + (size_t)row * DD);
    float ag = 0.f, au = 0.f;
#pragma unroll 2
    for (int i = lane; i < DD / 4; i += 32) {
        float4 v = sx4[i];
        float4 a = Wgr[i];
        ag = fmaf(a.x, v.x, ag); ag = fmaf(a.y, v.y, ag);
        ag = fmaf(a.z, v.z, ag); ag = fmaf(a.w, v.w, ag);
        float4 b = Wur[i];
        au = fmaf(b.x, v.x, au); au = fmaf(b.y, v.y, au);
        au = fmaf(b.z, v.z, au); au = fmaf(b.w, v.w, au);
    }
#pragma unroll
    for (int o = 16; o; o >>= 1) {
        ag += __shfl_xor_sync(0xffffffffu, ag, o);
        au += __shfl_xor_sync(0xffffffffu, au, o);
    }
    if (lane == 0) y[row] = gelu_tanh(ag) * au;
}

// ==================================================================================
extern "C" void kernel_launch(void* const* d_in, const int* in_sizes, int n_in,
                              void* d_out, int out_size) {
    const float* hidden = (const float*)d_in[0];
    const float* pls    = (const float*)d_in[3];
    const float* cos_s  = (const float*)d_in[4];
    const float* sin_s  = (const float*)d_in[5];
    const float* cos_f  = (const float*)d_in[6];
    const float* sin_f  = (const float*)d_in[7];
    const float* K_in   = (const float*)d_in[8];
    const float* V_in   = (const float*)d_in[9];
    const float* Wq     = (const float*)d_in[10];
    const float* Wk     = (const float*)d_in[11];
    const float* Wv     = (const float*)d_in[12];
    const float* Wo     = (const float*)d_in[13];
    const float* qn     = (const float*)d_in[14];
    const float* kn     = (const float*)d_in[15];
    const float* ln_in  = (const float*)d_in[16];
    const float* ln_pa  = (const float*)d_in[17];
    const float* ln_pre = (const float*)d_in[18];
    const float* ln_post= (const float*)d_in[19];
    const float* ln_pl  = (const float*)d_in[20];
    const float* Wg     = (const float*)d_in[21];
    const float* Wu     = (const float*)d_in[22];
    const float* Wd     = (const float*)d_in[23];
    const float* Wplg   = (const float*)d_in[24];
    const float* Wplp   = (const float*)d_in[25];
    const float* lsc    = (const float*)d_in[26];

    float* out  = (float*)d_out;
    float* outK = out + DD;
    float* outV = outK + (size_t)LL * KVH * SS * HDIM;

    float *h_, *hn_, *qkv_, *q_, *attn_, *ff_, *vec_, *pl_, *part_;
    unsigned* cnt_;
    cudaGetSymbolAddress((void**)&h_,    g_h);
    cudaGetSymbolAddress((void**)&hn_,   g_hn);
    cudaGetSymbolAddress((void**)&qkv_,  g_qkv);
    cudaGetSymbolAddress((void**)&q_,    g_q);
    cudaGetSymbolAddress((void**)&attn_, g_attn);
    cudaGetSymbolAddress((void**)&ff_,   g_ff);
    cudaGetSymbolAddress((void**)&vec_,  g_vec);
    cudaGetSymbolAddress((void**)&pl_,   g_pl);
    cudaGetSymbolAddress((void**)&part_, g_part);
    cudaGetSymbolAddress((void**)&cnt_,  g_cnt);

    const int kvN4 = LL * KVH * SS * HDIM / 4;
    copy_kv_kernel<<<4096, 256>>>((const float4*)K_in, (const float4*)V_in,
                                  (float4*)outK, (float4*)outV, kvN4);

    norm0_kernel<<<1, 256>>>(hidden, ln_in, h_, hn_);

    for (int l = 0; l < LL; l++) {
        const float* cosp = (l == 4) ? cos_f : cos_s;   // is_full only layer 4 (L=8)
        const float* sinp = (l == 4) ? sin_f : sin_s;

        const float* Wq_l   = Wq   + (size_t)l * HH * HDIM * DD;
        const float* Wk_l   = Wk   + (size_t)l * KVH * HDIM * DD;
        const float* Wv_l   = Wv   + (size_t)l * KVH * HDIM * DD;
        const float* Wo_l   = Wo   + (size_t)l * DD * HH * HDIM;
        const float* Wg_l   = Wg   + (size_t)l * FFD * DD;
        const float* Wu_l   = Wu   + (size_t)l * FFD * DD;
        const float* Wd_l   = Wd   + (size_t)l * DD * FFD;
        const float* Wplg_l = Wplg + (size_t)l * PLD * DD;
        const float* Wplp_l = Wplp + (size_t)l * DD * PLD;

        float* Kl   = outK + (size_t)l * KVH * SS * HDIM;
        float* Vl   = outV + (size_t)l * KVH * SS * HDIM;
        float* Kpos = Kl + (size_t)POSI * HDIM;
        float* Vpos = Vl + (size_t)POSI * HDIM;

        // attention block
        gemv_qkv_kernel<<<384, 256>>>(Wq_l, Wk_l, Wv_l, hn_, qkv_,
                                      qn + l * HDIM, kn + l * HDIM, cosp, sinp,
                                      q_, Kpos, Vpos, cnt_ + 0);
        attn_part_kernel<<<NSPL * HH, 256>>>(q_, Kl, Vl, part_, attn_);
        gemv_kernel<DD, 2><<<256, 256>>>(Wo_l, attn_, vec_, nullptr,
                                         ln_pa + l * DD, h_, ln_pre + l * DD, hn_,
                                         nullptr, nullptr, cnt_ + 1);
        // MLP block
        gemv_gated_kernel<<<1024, 256>>>(Wg_l, Wu_l, hn_, ff_);
        gemv_kernel<FFD, 2><<<256, 256>>>(Wd_l, ff_, vec_, nullptr,
                                          ln_post + l * DD, h_, nullptr, nullptr,
                                          nullptr, nullptr, cnt_ + 2);
        // per-layer embedding block (uses h directly)
        gemv_kernel<DD, 1><<<32, 256>>>(Wplg_l, h_, pl_, pls + l * PLD,
                                        nullptr, nullptr, nullptr, nullptr,
                                        nullptr, nullptr, nullptr);
        gemv_kernel<PLD, 3><<<256, 256>>>(Wplp_l, pl_, vec_, nullptr,
                                          ln_pl + l * DD, h_,
                                          (l < LL - 1) ? (ln_in + (l + 1) * DD) : nullptr, hn_,
                                          lsc + l, (l == LL - 1) ? out : nullptr, cnt_ + 3);
    }
}

// round 5
// speedup vs baseline: 1.0450x; 1.0450x over previous
#include <cuda_runtime.h>
#include <math.h>

#define DD   2048
#define HH   8
#define KVH  2
#define HDIM 256
#define SS   4096
#define FFD  8192
#define PLD  256
#define LL   8
#define POSI 2048
#define EPSF 1e-6f
#define NSPL 33
#define CHNK 64   // 33*64 = 2112 >= 2049 positions

// ---------------- scratch (device globals; no allocation allowed) ----------------
__device__ float g_h[DD];
__device__ float g_hn[DD];
__device__ float g_qkv[HH*HDIM + 2*KVH*HDIM];   // 3072
__device__ float g_q[HH*HDIM];
__device__ float g_knew[KVH*HDIM];
__device__ float g_vnew[KVH*HDIM];
__device__ float g_attn[HH*HDIM];
__device__ float g_ff[FFD];
__device__ float g_vec[DD];
__device__ float g_pl[PLD];
__device__ float g_part[HH * NSPL * (HDIM + 2)];
__device__ unsigned g_cnt[8];          // generic self-resetting tickets
__device__ unsigned g_cnt_attn[KVH];   // per-kv tickets

__device__ __forceinline__ float gelu_tanh(float x) {
    const float c = 0.7978845608028654f;
    return 0.5f * x * (1.0f + tanhf(c * (x + 0.044715f * x * x * x)));
}

__device__ __forceinline__ float warp_sum(float v) {
#pragma unroll
    for (int o = 16; o; o >>= 1) v += __shfl_xor_sync(0xffffffffu, v, o);
    return v;
}

__device__ __forceinline__ float warp_max(float v) {
#pragma unroll
    for (int o = 16; o; o >>= 1) v = fmaxf(v, __shfl_xor_sync(0xffffffffu, v, o));
    return v;
}

__device__ __forceinline__ float block_sum_256(float v, float* red) {
    int t = threadIdx.x;
    red[t] = v; __syncthreads();
    for (int s = 128; s > 0; s >>= 1) { if (t < s) red[t] += red[t + s]; __syncthreads(); }
    float r = red[0];
    __syncthreads();
    return r;
}

// store -> fence -> sync -> t0 atomic -> sync ; winner gets acquire fence
__device__ __forceinline__ bool last_block_ticket(unsigned* cnt, unsigned total) {
    __threadfence();
    __syncthreads();
    __shared__ unsigned isLast;
    if (threadIdx.x == 0) isLast = (atomicInc(cnt, total - 1) == total - 1);
    __syncthreads();
    if (!isLast) return false;
    __threadfence();
    return true;
}

// ---------------- KV cache bulk copy, SKIPPING row POSI of each plane ----------------
// (row POSI is written exclusively by the QKV epilogue -> no cross-stream race)
__global__ void __launch_bounds__(256) copy_kv_kernel(
        const float4* __restrict__ Ki, const float4* __restrict__ Vi,
        float4* __restrict__ Ko, float4* __restrict__ Vo, int n4) {
    int stride = gridDim.x * blockDim.x;
    for (int i = blockIdx.x * blockDim.x + threadIdx.x; i < n4; i += stride) {
        bool skip = (((i >> 6) & (SS - 1)) == POSI);   // 64 float4 per row, SS rows/plane
        if (!skip) {
            Ko[i] = Ki[i];
            Vo[i] = Vi[i];
        }
    }
}

// ---------------- h = hidden (copy) ; hn = rms(h) * w ----------------
__global__ void norm0_kernel(const float* __restrict__ hidden, const float* __restrict__ w,
                             float* __restrict__ h, float* __restrict__ hn) {
    __shared__ float red[256];
    int t = threadIdx.x;
    float hv[8]; float ss = 0.f;
#pragma unroll
    for (int j = 0; j < 8; j++) { hv[j] = hidden[t + j * 256]; ss += hv[j] * hv[j]; }
    ss = block_sum_256(ss, red);
    float r = rsqrtf(ss / (float)DD + EPSF);
#pragma unroll
    for (int j = 0; j < 8; j++) { int i = t + j * 256; h[i] = hv[j]; hn[i] = hv[j] * r * w[i]; }
}

// ---------------- fused QKV GEMV + (last block) per-head RMS/RoPE/cache-write ----------
__global__ void __launch_bounds__(256) gemv_qkv_kernel(
        const float* __restrict__ Wq, const float* __restrict__ Wk, const float* __restrict__ Wv,
        const float* __restrict__ x, float* __restrict__ y,
        const float* __restrict__ qn, const float* __restrict__ kn,
        const float* __restrict__ cosv, const float* __restrict__ sinv,
        float* __restrict__ q_out, float* __restrict__ knew, float* __restrict__ vnew,
        float* __restrict__ Kpos, float* __restrict__ Vpos,
        unsigned* __restrict__ cnt) {
    __shared__ float4 sx4[DD / 4];
    const float4* x4 = (const float4*)x;
    for (int i = threadIdx.x; i < DD / 4; i += 256) sx4[i] = x4[i];
    __syncthreads();
    int row = blockIdx.x * 8 + (threadIdx.x >> 5);
    int lane = threadIdx.x & 31;
    const float* W; int r;
    if (row < 2048)      { W = Wq; r = row; }
    else if (row < 2560) { W = Wk; r = row - 2048; }
    else                 { W = Wv; r = row - 2560; }
    const float4* Wr = (const float4*)(W + (size_t)r * DD);
    float acc = 0.f;
#pragma unroll 8
    for (int i = lane; i < DD / 4; i += 32) {
        float4 w = Wr[i]; float4 v = sx4[i];
        acc = fmaf(w.x, v.x, acc); acc = fmaf(w.y, v.y, acc);
        acc = fmaf(w.z, v.z, acc); acc = fmaf(w.w, v.w, acc);
    }
    acc = warp_sum(acc);
    if (lane == 0) y[row] = acc;

    if (!last_block_ticket(cnt, gridDim.x)) return;

    int warp = threadIdx.x >> 5;
    for (int u = warp; u < 12; u += 8) {
        const float* src; const float* nw = nullptr; int rope = 1;
        if (u < 8)        { src = y + u * HDIM; nw = qn; }
        else if (u < 10)  { src = y + HH * HDIM + (u - 8) * HDIM; nw = kn; }
        else              { src = y + HH * HDIM + KVH * HDIM + (u - 10) * HDIM; rope = 0; }
        float v8[8]; float ss = 0.f;
#pragma unroll
        for (int j = 0; j < 8; j++) { v8[j] = src[lane * 8 + j]; ss += v8[j] * v8[j]; }
        ss = warp_sum(ss);
        float rr = rsqrtf(ss / (float)HDIM + EPSF);
#pragma unroll
        for (int j = 0; j < 8; j++) {
            int d = lane * 8 + j;
            float val = v8[j] * rr;
            if (nw) val *= nw[d];
            if (rope) {
                int p = (d < 128) ? d + 128 : d - 128;
                float pv = src[p] * rr * (nw ? nw[p] : 1.f);
                float rot = (d < 128) ? -pv : pv;
                val = val * cosv[d] + rot * sinv[d];
            }
            if (u < 8)       q_out[u * HDIM + d] = val;
            else if (u < 10) {
                int kv = u - 8;
                knew[kv * HDIM + d] = val;
                Kpos[(size_t)kv * SS * HDIM + d] = val;
            } else {
                int kv = u - 10;
                vnew[kv * HDIM + d] = val;
                Vpos[(size_t)kv * SS * HDIM + d] = val;
            }
        }
    }
}

// ---------------- attention: block = (kv, chunk); 4 q-heads share K/V reads -----------
__global__ void __launch_bounds__(256) attn_part_kernel(
        const float* __restrict__ q,
        const float* __restrict__ Kin, const float* __restrict__ Vin,  // layer planes (const input)
        const float* __restrict__ knew, const float* __restrict__ vnew,
        float* __restrict__ part, float* __restrict__ out) {
    int kv = blockIdx.x & 1;
    int chunk = blockIdx.x >> 1;
    const float* Kh = Kin + (size_t)kv * SS * HDIM;
    const float* Vh = Vin + (size_t)kv * SS * HDIM;
    const float* kn_ = knew + kv * HDIM;
    const float* vn_ = vnew + kv * HDIM;
    int t = threadIdx.x;
    int warp = t >> 5, lane = t & 31;
    int s0 = chunk * CHNK;
    int n = min(CHNK, POSI + 1 - s0);

    __shared__ float sq[4][HDIM];
    __shared__ float ssc[4][CHNK];
    __shared__ float swm[8], sws[8];
    __shared__ float sM[4], sL[4];
#pragma unroll
    for (int hh = 0; hh < 4; hh++) sq[hh][t] = q[(kv * 4 + hh) * HDIM + t];
    __syncthreads();

    float qreg[4][8];
#pragma unroll
    for (int hh = 0; hh < 4; hh++)
#pragma unroll
        for (int j = 0; j < 8; j++) qreg[hh][j] = sq[hh][lane * 8 + j];

    // Phase A: scores, warp per position, 4 heads per K-row read
#pragma unroll 2
    for (int idx = warp; idx < n; idx += 8) {
        int s = s0 + idx;
        const float* Kr = (s == POSI) ? kn_ : (Kh + (size_t)s * HDIM);
        float4 ka = *(const float4*)(Kr + lane * 8);
        float4 kb = *(const float4*)(Kr + lane * 8 + 4);
        float k8[8] = {ka.x, ka.y, ka.z, ka.w, kb.x, kb.y, kb.z, kb.w};
        float d0 = 0.f, d1 = 0.f, d2 = 0.f, d3 = 0.f;
#pragma unroll
        for (int j = 0; j < 8; j++) {
            d0 = fmaf(k8[j], qreg[0][j], d0);
            d1 = fmaf(k8[j], qreg[1][j], d1);
            d2 = fmaf(k8[j], qreg[2][j], d2);
            d3 = fmaf(k8[j], qreg[3][j], d3);
        }
        d0 = warp_sum(d0); d1 = warp_sum(d1);
        d2 = warp_sum(d2); d3 = warp_sum(d3);
        if (lane == 0) { ssc[0][idx] = d0; ssc[1][idx] = d1; ssc[2][idx] = d2; ssc[3][idx] = d3; }
    }
    __syncthreads();

    // Phase B: softmax per head over this chunk (64 threads per head)
    int hh = t >> 6, p = t & 63;
    float val = (p < n) ? ssc[hh][p] : -1e30f;
    float wm = warp_max(val);
    if (lane == 0) swm[warp] = wm;
    __syncthreads();
    float M = fmaxf(swm[2 * hh], swm[2 * hh + 1]);
    float e = (p < n) ? expf(val - M) : 0.f;
    float ws = warp_sum(e);
    if (lane == 0) sws[warp] = ws;
    __syncthreads();
    float L = sws[2 * hh] + sws[2 * hh + 1];
    if (p < n) ssc[hh][p] = e;
    if (p == 0) { sM[hh] = M; sL[hh] = L; }
    __syncthreads();

    // Phase C: V accumulation, thread = dim, 4 heads per V read
    float a0 = 0.f, a1 = 0.f, a2 = 0.f, a3 = 0.f;
#pragma unroll 8
    for (int idx = 0; idx < n; idx++) {
        int s = s0 + idx;
        const float* Vr = (s == POSI) ? vn_ : (Vh + (size_t)s * HDIM);
        float v = Vr[t];
        a0 = fmaf(ssc[0][idx], v, a0);
        a1 = fmaf(ssc[1][idx], v, a1);
        a2 = fmaf(ssc[2][idx], v, a2);
        a3 = fmaf(ssc[3][idx], v, a3);
    }
    float accs[4] = {a0, a1, a2, a3};
#pragma unroll
    for (int u = 0; u < 4; u++) {
        float* pp = part + (size_t)((kv * 4 + u) * NSPL + chunk) * (HDIM + 2);
        pp[t] = accs[u];
        if (t == 0) { pp[HDIM] = sM[u]; pp[HDIM + 1] = sL[u]; }
    }

    // ---- last chunk for this kv: combine all 4 heads ----
    if (!last_block_ticket(&g_cnt_attn[kv], NSPL)) return;
    __shared__ float cf[4][NSPL];
    __shared__ float cLg[4];
    // factors
    if (t < 4 * NSPL) {
        int u = t / NSPL, c = t % NSPL;
        cf[u][c] = part[(size_t)((kv * 4 + u) * NSPL + c) * (HDIM + 2) + HDIM];  // M for now
    }
    __syncthreads();
    if (t < 4) {
        float Mg = -1e30f;
        for (int c = 0; c < NSPL; c++) Mg = fmaxf(Mg, cf[t][c]);
        float Lg = 0.f;
        for (int c = 0; c < NSPL; c++) {
            const float* pp = part + (size_t)((kv * 4 + t) * NSPL + c) * (HDIM + 2);
            float f = expf(pp[HDIM] - Mg);
            Lg += pp[HDIM + 1] * f;
            cf[t][c] = f;
        }
        cLg[t] = Lg;
    }
    __syncthreads();
#pragma unroll
    for (int u = 0; u < 4; u++) {
        float num = 0.f;
        for (int c = 0; c < NSPL; c++)
            num = fmaf(part[(size_t)((kv * 4 + u) * NSPL + c) * (HDIM + 2) + t], cf[u][c], num);
        out[(kv * 4 + u) * HDIM + t] = num / cLg[u];
    }
}

// ---------------- generic GEMV, 256 thr / 8 rows, optional fused epilogue --------
// MODE 0: y = Wx ; MODE 1: y = gelu(Wx)*aux
// MODE 2: + last block: h += rms(y)*w1 ; if (w2) hn = rms(h)*w2
// MODE 3: + last block: h = (h + rms(y)*w1)*sc ; if (w2) hn = rms(h)*w2 ; if (out2) out2 = h
template<int COLS, int MODE>
__global__ void __launch_bounds__(256) gemv_kernel(
        const float* __restrict__ W, const float* __restrict__ x, float* __restrict__ y,
        const float* __restrict__ aux,
        const float* __restrict__ w1, float* __restrict__ h,
        const float* __restrict__ w2, float* __restrict__ hn,
        const float* __restrict__ scp, float* __restrict__ out2,
        unsigned* __restrict__ cnt) {
    __shared__ float4 sx4[COLS / 4];
    const float4* x4 = (const float4*)x;
    for (int i = threadIdx.x; i < COLS / 4; i += 256) sx4[i] = x4[i];
    __syncthreads();
    int row = blockIdx.x * 8 + (threadIdx.x >> 5);
    int lane = threadIdx.x & 31;
    const float4* Wr = (const float4*)(W + (size_t)row * COLS);
    float acc = 0.f;
#pragma unroll 8
    for (int i = lane; i < COLS / 4; i += 32) {
        float4 w = Wr[i]; float4 v = sx4[i];
        acc = fmaf(w.x, v.x, acc); acc = fmaf(w.y, v.y, acc);
        acc = fmaf(w.z, v.z, acc); acc = fmaf(w.w, v.w, acc);
    }
    acc = warp_sum(acc);
    if (lane == 0) {
        if (MODE == 1) acc = gelu_tanh(acc) * aux[row];
        y[row] = acc;
    }
    if (MODE < 2) return;

    if (!last_block_ticket(cnt, gridDim.x)) return;

    __shared__ float red[256];
    int t = threadIdx.x;
    float vv[8], hv[8]; float ss = 0.f;
#pragma unroll
    for (int j = 0; j < 8; j++) { int i = t + j * 256; vv[j] = y[i]; ss += vv[j] * vv[j]; }
    ss = block_sum_256(ss, red);
    float r1 = rsqrtf(ss / (float)DD + EPSF);
    float sc = (MODE == 3) ? scp[0] : 1.f;
    float ss2 = 0.f;
#pragma unroll
    for (int j = 0; j < 8; j++) {
        int i = t + j * 256;
        float nh = h[i] + vv[j] * r1 * w1[i];
        if (MODE == 3) nh *= sc;
        hv[j] = nh;
        h[i] = nh;
        if (MODE == 3 && out2) out2[i] = nh;
        ss2 += nh * nh;
    }
    if (w2) {
        ss2 = block_sum_256(ss2, red);
        float r2 = rsqrtf(ss2 / (float)DD + EPSF);
#pragma unroll
        for (int j = 0; j < 8; j++) { int i = t + j * 256; hn[i] = hv[j] * r2 * w2[i]; }
    }
}

// ---------------- fused gated MLP GEMV: y = gelu(Wg x) * (Wu x) ----------------
__global__ void __launch_bounds__(256) gemv_gated_kernel(
        const float* __restrict__ Wg, const float* __restrict__ Wu,
        const float* __restrict__ x, float* __restrict__ y) {
    __shared__ float4 sx4[DD / 4];
    const float4* x4 = (const float4*)x;
    for (int i = threadIdx.x; i < DD / 4; i += 256) sx4[i] = x4[i];
    __syncthreads();
    int row = blockIdx.x * 8 + (threadIdx.x >> 5);
    int lane = threadIdx.x & 31;
    const float4* Wgr = (const float4*)(Wg + (size_t)row * DD);
    const float4* Wur = (const float4*)(Wu + (size_t)row * DD);
    float ag = 0.f, au = 0.f;
#pragma unroll 4
    for (int i = lane; i < DD / 4; i += 32) {
        float4 v = sx4[i];
        float4 a = Wgr[i];
        ag = fmaf(a.x, v.x, ag); ag = fmaf(a.y, v.y, ag);
        ag = fmaf(a.z, v.z, ag); ag = fmaf(a.w, v.w, ag);
        float4 b = Wur[i];
        au = fmaf(b.x, v.x, au); au = fmaf(b.y, v.y, au);
        au = fmaf(b.z, v.z, au); au = fmaf(b.w, v.w, au);
    }
#pragma unroll
    for (int o = 16; o; o >>= 1) {
        ag += __shfl_xor_sync(0xffffffffu, ag, o);
        au += __shfl_xor_sync(0xffffffffu, au, o);
    }
    if (lane == 0) y[row] = gelu_tanh(ag) * au;
}

// ==================================================================================
extern "C" void kernel_launch(void* const* d_in, const int* in_sizes, int n_in,
                              void* d_out, int out_size) {
    const float* hidden = (const float*)d_in[0];
    const float* pls    = (const float*)d_in[3];
    const float* cos_s  = (const float*)d_in[4];
    const float* sin_s  = (const float*)d_in[5];
    const float* cos_f  = (const float*)d_in[6];
    const float* sin_f  = (const float*)d_in[7];
    const float* K_in   = (const float*)d_in[8];
    const float* V_in   = (const float*)d_in[9];
    const float* Wq     = (const float*)d_in[10];
    const float* Wk     = (const float*)d_in[11];
    const float* Wv     = (const float*)d_in[12];
    const float* Wo     = (const float*)d_in[13];
    const float* qn     = (const float*)d_in[14];
    const float* kn     = (const float*)d_in[15];
    const float* ln_in  = (const float*)d_in[16];
    const float* ln_pa  = (const float*)d_in[17];
    const float* ln_pre = (const float*)d_in[18];
    const float* ln_post= (const float*)d_in[19];
    const float* ln_pl  = (const float*)d_in[20];
    const float* Wg     = (const float*)d_in[21];
    const float* Wu     = (const float*)d_in[22];
    const float* Wd     = (const float*)d_in[23];
    const float* Wplg   = (const float*)d_in[24];
    const float* Wplp   = (const float*)d_in[25];
    const float* lsc    = (const float*)d_in[26];

    float* out  = (float*)d_out;
    float* outK = out + DD;
    float* outV = outK + (size_t)LL * KVH * SS * HDIM;

    float *h_, *hn_, *qkv_, *q_, *knew_, *vnew_, *attn_, *ff_, *vec_, *pl_, *part_;
    unsigned* cnt_;
    cudaGetSymbolAddress((void**)&h_,    g_h);
    cudaGetSymbolAddress((void**)&hn_,   g_hn);
    cudaGetSymbolAddress((void**)&qkv_,  g_qkv);
    cudaGetSymbolAddress((void**)&q_,    g_q);
    cudaGetSymbolAddress((void**)&knew_, g_knew);
    cudaGetSymbolAddress((void**)&vnew_, g_vnew);
    cudaGetSymbolAddress((void**)&attn_, g_attn);
    cudaGetSymbolAddress((void**)&ff_,   g_ff);
    cudaGetSymbolAddress((void**)&vec_,  g_vec);
    cudaGetSymbolAddress((void**)&pl_,   g_pl);
    cudaGetSymbolAddress((void**)&part_, g_part);
    cudaGetSymbolAddress((void**)&cnt_,  g_cnt);

    // lazily-created side stream + events for capture-fork (host objects only)
    static cudaStream_t side = nullptr;
    static cudaEvent_t evFork = nullptr, evJoin = nullptr;
    if (!side) {
        cudaStreamCreateWithFlags(&side, cudaStreamNonBlocking);
        cudaEventCreateWithFlags(&evFork, cudaEventDisableTiming);
        cudaEventCreateWithFlags(&evJoin, cudaEventDisableTiming);
    }

    // fork: KV bulk copy overlaps the entire layer loop (compute never reads outK/outV)
    cudaEventRecord(evFork, 0);
    cudaStreamWaitEvent(side, evFork, 0);
    const int kvN4 = LL * KVH * SS * HDIM / 4;
    copy_kv_kernel<<<4096, 256, 0, side>>>((const float4*)K_in, (const float4*)V_in,
                                           (float4*)outK, (float4*)outV, kvN4);
    cudaEventRecord(evJoin, side);

    norm0_kernel<<<1, 256>>>(hidden, ln_in, h_, hn_);

    for (int l = 0; l < LL; l++) {
        const float* cosp = (l == 4) ? cos_f : cos_s;   // is_full only layer 4 (L=8)
        const float* sinp = (l == 4) ? sin_f : sin_s;

        const float* Wq_l   = Wq   + (size_t)l * HH * HDIM * DD;
        const float* Wk_l   = Wk   + (size_t)l * KVH * HDIM * DD;
        const float* Wv_l   = Wv   + (size_t)l * KVH * HDIM * DD;
        const float* Wo_l   = Wo   + (size_t)l * DD * HH * HDIM;
        const float* Wg_l   = Wg   + (size_t)l * FFD * DD;
        const float* Wu_l   = Wu   + (size_t)l * FFD * DD;
        const float* Wd_l   = Wd   + (size_t)l * DD * FFD;
        const float* Wplg_l = Wplg + (size_t)l * PLD * DD;
        const float* Wplp_l = Wplp + (size_t)l * DD * PLD;

        const float* Kin_l = K_in + (size_t)l * KVH * SS * HDIM;
        const float* Vin_l = V_in + (size_t)l * KVH * SS * HDIM;
        float* Kpos = outK + (size_t)l * KVH * SS * HDIM + (size_t)POSI * HDIM;
        float* Vpos = outV + (size_t)l * KVH * SS * HDIM + (size_t)POSI * HDIM;

        // attention block
        gemv_qkv_kernel<<<384, 256>>>(Wq_l, Wk_l, Wv_l, hn_, qkv_,
                                      qn + l * HDIM, kn + l * HDIM, cosp, sinp,
                                      q_, knew_, vnew_, Kpos, Vpos, cnt_ + 0);
        attn_part_kernel<<<KVH * NSPL, 256>>>(q_, Kin_l, Vin_l, knew_, vnew_, part_, attn_);
        gemv_kernel<DD, 2><<<256, 256>>>(Wo_l, attn_, vec_, nullptr,
                                         ln_pa + l * DD, h_, ln_pre + l * DD, hn_,
                                         nullptr, nullptr, cnt_ + 1);
        // MLP block
        gemv_gated_kernel<<<1024, 256>>>(Wg_l, Wu_l, hn_, ff_);
        gemv_kernel<FFD, 2><<<256, 256>>>(Wd_l, ff_, vec_, nullptr,
                                          ln_post + l * DD, h_, nullptr, nullptr,
                                          nullptr, nullptr, cnt_ + 2);
        // per-layer embedding block (uses h directly)
        gemv_kernel<DD, 1><<<32, 256>>>(Wplg_l, h_, pl_, pls + l * PLD,
                                        nullptr, nullptr, nullptr, nullptr,
                                        nullptr, nullptr, nullptr);
        gemv_kernel<PLD, 3><<<256, 256>>>(Wplp_l, pl_, vec_, nullptr,
                                          ln_pl + l * DD, h_,
                                          (l < LL - 1) ? (ln_in + (l + 1) * DD) : nullptr, hn_,
                                          lsc + l, (l == LL - 1) ? out : nullptr, cnt_ + 3);
    }

    // join: copy must be complete before kernel_launch's work is "done"
    cudaStreamWaitEvent(0, evJoin, 0);
}

// round 6
// speedup vs baseline: 1.1019x; 1.0544x over previous
#include <cuda_runtime.h>
#include <math.h>

#define DD   2048
#define HH   8
#define KVH  2
#define HDIM 256
#define SS   4096
#define FFD  8192
#define PLD  256
#define LL   8
#define POSI 2048
#define EPSF 1e-6f
#define NSPL 65
#define CHNK 32   // 65*32 = 2080 >= 2049 positions

// ---------------- scratch (device globals; no allocation allowed) ----------------
__device__ float g_h[DD];
__device__ float g_hn[DD];
__device__ float g_qkv[HH*HDIM + 2*KVH*HDIM];   // 3072
__device__ float g_q[HH*HDIM];
__device__ float g_knew[KVH*HDIM];
__device__ float g_vnew[KVH*HDIM];
__device__ float g_attn[HH*HDIM];
__device__ float g_ff2[2*FFD];
__device__ float g_vec[DD];
__device__ float g_pl[PLD];
__device__ float g_part[HH * NSPL * (HDIM + 2)];
__device__ unsigned g_cnt[8];          // generic self-resetting tickets
__device__ unsigned g_cnt_attn[KVH];   // per-kv tickets

__device__ __forceinline__ float gelu_tanh(float x) {
    const float c = 0.7978845608028654f;
    return 0.5f * x * (1.0f + tanhf(c * (x + 0.044715f * x * x * x)));
}

__device__ __forceinline__ float warp_sum(float v) {
#pragma unroll
    for (int o = 16; o; o >>= 1) v += __shfl_xor_sync(0xffffffffu, v, o);
    return v;
}

__device__ __forceinline__ float warp_max(float v) {
#pragma unroll
    for (int o = 16; o; o >>= 1) v = fmaxf(v, __shfl_xor_sync(0xffffffffu, v, o));
    return v;
}

__device__ __forceinline__ float block_sum_256(float v, float* red) {
    int t = threadIdx.x;
    red[t] = v; __syncthreads();
    for (int s = 128; s > 0; s >>= 1) { if (t < s) red[t] += red[t + s]; __syncthreads(); }
    float r = red[0];
    __syncthreads();
    return r;
}

// store -> fence -> sync -> t0 atomic -> sync ; winner gets acquire fence
__device__ __forceinline__ bool last_block_ticket(unsigned* cnt, unsigned total) {
    __threadfence();
    __syncthreads();
    __shared__ unsigned isLast;
    if (threadIdx.x == 0) isLast = (atomicInc(cnt, total - 1) == total - 1);
    __syncthreads();
    if (!isLast) return false;
    __threadfence();
    return true;
}

// ---------------- KV cache bulk copy, SKIPPING row POSI of each plane ----------------
__global__ void __launch_bounds__(256) copy_kv_kernel(
        const float4* __restrict__ Ki, const float4* __restrict__ Vi,
        float4* __restrict__ Ko, float4* __restrict__ Vo, int n4) {
    int stride = gridDim.x * blockDim.x;
    for (int i = blockIdx.x * blockDim.x + threadIdx.x; i < n4; i += stride) {
        bool skip = (((i >> 6) & (SS - 1)) == POSI);   // 64 float4 per row
        if (!skip) {
            Ko[i] = Ki[i];
            Vo[i] = Vi[i];
        }
    }
}

// ---------------- h = hidden (copy) ; hn = rms(h) * w ----------------
__global__ void norm0_kernel(const float* __restrict__ hidden, const float* __restrict__ w,
                             float* __restrict__ h, float* __restrict__ hn) {
    __shared__ float red[256];
    int t = threadIdx.x;
    float hv[8]; float ss = 0.f;
#pragma unroll
    for (int j = 0; j < 8; j++) { hv[j] = hidden[t + j * 256]; ss += hv[j] * hv[j]; }
    ss = block_sum_256(ss, red);
    float r = rsqrtf(ss / (float)DD + EPSF);
#pragma unroll
    for (int j = 0; j < 8; j++) { int i = t + j * 256; h[i] = hv[j]; hn[i] = hv[j] * r * w[i]; }
}

// ---------------- fused QKV GEMV + (last block) per-head RMS/RoPE/cache-write ----------
__global__ void __launch_bounds__(256) gemv_qkv_kernel(
        const float* __restrict__ Wq, const float* __restrict__ Wk, const float* __restrict__ Wv,
        const float* __restrict__ x, float* __restrict__ y,
        const float* __restrict__ qn, const float* __restrict__ kn,
        const float* __restrict__ cosv, const float* __restrict__ sinv,
        float* __restrict__ q_out, float* __restrict__ knew, float* __restrict__ vnew,
        float* __restrict__ Kpos, float* __restrict__ Vpos,
        unsigned* __restrict__ cnt) {
    __shared__ float4 sx4[DD / 4];
    const float4* x4 = (const float4*)x;
    for (int i = threadIdx.x; i < DD / 4; i += 256) sx4[i] = x4[i];
    __syncthreads();
    int row = blockIdx.x * 8 + (threadIdx.x >> 5);
    int lane = threadIdx.x & 31;
    const float* W; int r;
    if (row < 2048)      { W = Wq; r = row; }
    else if (row < 2560) { W = Wk; r = row - 2048; }
    else                 { W = Wv; r = row - 2560; }
    const float4* Wr = (const float4*)(W + (size_t)r * DD);
    float acc = 0.f;
#pragma unroll 8
    for (int i = lane; i < DD / 4; i += 32) {
        float4 w = Wr[i]; float4 v = sx4[i];
        acc = fmaf(w.x, v.x, acc); acc = fmaf(w.y, v.y, acc);
        acc = fmaf(w.z, v.z, acc); acc = fmaf(w.w, v.w, acc);
    }
    acc = warp_sum(acc);
    if (lane == 0) y[row] = acc;

    if (!last_block_ticket(cnt, gridDim.x)) return;

    int warp = threadIdx.x >> 5;
    for (int u = warp; u < 12; u += 8) {
        const float* src; const float* nw = nullptr; int rope = 1;
        if (u < 8)        { src = y + u * HDIM; nw = qn; }
        else if (u < 10)  { src = y + HH * HDIM + (u - 8) * HDIM; nw = kn; }
        else              { src = y + HH * HDIM + KVH * HDIM + (u - 10) * HDIM; rope = 0; }
        float v8[8]; float ss = 0.f;
#pragma unroll
        for (int j = 0; j < 8; j++) { v8[j] = src[lane * 8 + j]; ss += v8[j] * v8[j]; }
        ss = warp_sum(ss);
        float rr = rsqrtf(ss / (float)HDIM + EPSF);
#pragma unroll
        for (int j = 0; j < 8; j++) {
            int d = lane * 8 + j;
            float val = v8[j] * rr;
            if (nw) val *= nw[d];
            if (rope) {
                int p = (d < 128) ? d + 128 : d - 128;
                float pv = src[p] * rr * (nw ? nw[p] : 1.f);
                float rot = (d < 128) ? -pv : pv;
                val = val * cosv[d] + rot * sinv[d];
            }
            if (u < 8)       q_out[u * HDIM + d] = val;
            else if (u < 10) {
                int kv = u - 8;
                knew[kv * HDIM + d] = val;
                Kpos[(size_t)kv * SS * HDIM + d] = val;
            } else {
                int kv = u - 10;
                vnew[kv * HDIM + d] = val;
                Vpos[(size_t)kv * SS * HDIM + d] = val;
            }
        }
    }
}

// ---------------- attention: block = (kv, chunk of 32); 4 q-heads share K/V reads ----------
__global__ void __launch_bounds__(256) attn_part_kernel(
        const float* __restrict__ q,
        const float* __restrict__ Kin, const float* __restrict__ Vin,
        const float* __restrict__ knew, const float* __restrict__ vnew,
        float* __restrict__ part, float* __restrict__ out) {
    int kv = blockIdx.x & 1;
    int chunk = blockIdx.x >> 1;
    const float* Kh = Kin + (size_t)kv * SS * HDIM;
    const float* Vh = Vin + (size_t)kv * SS * HDIM;
    const float* kn_ = knew + kv * HDIM;
    const float* vn_ = vnew + kv * HDIM;
    int t = threadIdx.x;
    int warp = t >> 5, lane = t & 31;
    int s0 = chunk * CHNK;
    int n = min(CHNK, POSI + 1 - s0);

    __shared__ float sq[4][HDIM];
    __shared__ float ssc[4][CHNK];
    __shared__ float sM[4], sL[4];
    __shared__ float spart[4][4][HDIM];   // [group][head][dim]
#pragma unroll
    for (int hh = 0; hh < 4; hh++) sq[hh][t] = q[(kv * 4 + hh) * HDIM + t];
    __syncthreads();

    float qreg[4][8];
#pragma unroll
    for (int hh = 0; hh < 4; hh++)
#pragma unroll
        for (int j = 0; j < 8; j++) qreg[hh][j] = sq[hh][lane * 8 + j];

    // Phase A: scores, warp per position (max 4 iterations), 4 heads per K read
    for (int idx = warp; idx < n; idx += 8) {
        int s = s0 + idx;
        const float* Kr = (s == POSI) ? kn_ : (Kh + (size_t)s * HDIM);
        float4 ka = *(const float4*)(Kr + lane * 8);
        float4 kb = *(const float4*)(Kr + lane * 8 + 4);
        float k8[8] = {ka.x, ka.y, ka.z, ka.w, kb.x, kb.y, kb.z, kb.w};
        float d0 = 0.f, d1 = 0.f, d2 = 0.f, d3 = 0.f;
#pragma unroll
        for (int j = 0; j < 8; j++) {
            d0 = fmaf(k8[j], qreg[0][j], d0);
            d1 = fmaf(k8[j], qreg[1][j], d1);
            d2 = fmaf(k8[j], qreg[2][j], d2);
            d3 = fmaf(k8[j], qreg[3][j], d3);
        }
        d0 = warp_sum(d0); d1 = warp_sum(d1);
        d2 = warp_sum(d2); d3 = warp_sum(d3);
        if (lane == 0) { ssc[0][idx] = d0; ssc[1][idx] = d1; ssc[2][idx] = d2; ssc[3][idx] = d3; }
    }
    __syncthreads();

    // Phase B: per-head softmax over <=32 positions (warp per head)
    if (warp < 4) {
        float val = (lane < n) ? ssc[warp][lane] : -1e30f;
        float M = warp_max(val);
        float e = (lane < n) ? expf(val - M) : 0.f;
        float L = warp_sum(e);
        if (lane < n) ssc[warp][lane] = e;
        if (lane == 0) { sM[warp] = M; sL[warp] = L; }
    }
    __syncthreads();

    // Phase C: V accumulation; 4 position-groups in parallel, float4 V loads
    int g = t >> 6;            // group 0..3 handles positions g, g+4, g+8, ...
    int d4 = (t & 63);         // float4 index within row (dims d4*4..d4*4+3)
    float acc[4][4];
#pragma unroll
    for (int u = 0; u < 4; u++)
#pragma unroll
        for (int j = 0; j < 4; j++) acc[u][j] = 0.f;
#pragma unroll 2
    for (int idx = g; idx < n; idx += 4) {
        int s = s0 + idx;
        const float4* Vr4 = (const float4*)((s == POSI) ? vn_ : (Vh + (size_t)s * HDIM));
        float4 v = Vr4[d4];
#pragma unroll
        for (int u = 0; u < 4; u++) {
            float p = ssc[u][idx];
            acc[u][0] = fmaf(p, v.x, acc[u][0]);
            acc[u][1] = fmaf(p, v.y, acc[u][1]);
            acc[u][2] = fmaf(p, v.z, acc[u][2]);
            acc[u][3] = fmaf(p, v.w, acc[u][3]);
        }
    }
#pragma unroll
    for (int u = 0; u < 4; u++)
        *(float4*)&spart[g][u][d4 * 4] = make_float4(acc[u][0], acc[u][1], acc[u][2], acc[u][3]);
    __syncthreads();

    // cross-group reduce + write partials (thread = dim)
#pragma unroll
    for (int u = 0; u < 4; u++) {
        float num = spart[0][u][t] + spart[1][u][t] + spart[2][u][t] + spart[3][u][t];
        float* pp = part + (size_t)((kv * 4 + u) * NSPL + chunk) * (HDIM + 2);
        pp[t] = num;
        if (t == 0) { pp[HDIM] = sM[u]; pp[HDIM + 1] = sL[u]; }
    }

    // ---- last chunk for this kv: combine all 4 heads ----
    if (!last_block_ticket(&g_cnt_attn[kv], NSPL)) return;
    __shared__ float cf[4][NSPL];
    __shared__ float cLg[4];
    if (t < 4) {
        float Mg = -1e30f;
        for (int c = 0; c < NSPL; c++)
            Mg = fmaxf(Mg, part[(size_t)((kv * 4 + t) * NSPL + c) * (HDIM + 2) + HDIM]);
        float Lg = 0.f;
        for (int c = 0; c < NSPL; c++) {
            const float* pp = part + (size_t)((kv * 4 + t) * NSPL + c) * (HDIM + 2);
            float f = expf(pp[HDIM] - Mg);
            Lg += pp[HDIM + 1] * f;
            cf[t][c] = f;
        }
        cLg[t] = Lg;
    }
    __syncthreads();
#pragma unroll
    for (int u = 0; u < 4; u++) {
        float num = 0.f;
        for (int c = 0; c < NSPL; c++)
            num = fmaf(part[(size_t)((kv * 4 + u) * NSPL + c) * (HDIM + 2) + t], cf[u][c], num);
        out[(kv * 4 + u) * HDIM + t] = num / cLg[u];
    }
}

// ---------------- dual-matrix GEMV for Wg/Wu: rows [0,FFD)=Wg, [FFD,2FFD)=Wu ------------
__global__ void __launch_bounds__(256) gemv_wgwu_kernel(
        const float* __restrict__ Wg, const float* __restrict__ Wu,
        const float* __restrict__ x, float* __restrict__ y) {
    __shared__ float4 sx4[DD / 4];
    const float4* x4 = (const float4*)x;
    for (int i = threadIdx.x; i < DD / 4; i += 256) sx4[i] = x4[i];
    __syncthreads();
    int row = blockIdx.x * 8 + (threadIdx.x >> 5);
    int lane = threadIdx.x & 31;
    const float* W; int r;
    if (row < FFD) { W = Wg; r = row; } else { W = Wu; r = row - FFD; }
    const float4* Wr = (const float4*)(W + (size_t)r * DD);
    float acc = 0.f;
#pragma unroll 8
    for (int i = lane; i < DD / 4; i += 32) {
        float4 w = Wr[i]; float4 v = sx4[i];
        acc = fmaf(w.x, v.x, acc); acc = fmaf(w.y, v.y, acc);
        acc = fmaf(w.z, v.z, acc); acc = fmaf(w.w, v.w, acc);
    }
    acc = warp_sum(acc);
    if (lane == 0) y[row] = acc;
}

// ---------------- generic GEMV, 256 thr / 8 rows, optional gate-staging + fused epilogue ----
// GATE: x has 2*COLS elements; staged x[i] = gelu(x[i]) * x[i+COLS]
// MODE 0: y = Wx ; MODE 1: y = gelu(Wx)*aux
// MODE 2: + last block: h += rms(y)*w1 ; if (w2) hn = rms(h)*w2
// MODE 3: + last block: h = (h + rms(y)*w1)*sc ; if (w2) hn = rms(h)*w2 ; if (out2) out2 = h
template<int COLS, int MODE, int GATE>
__global__ void __launch_bounds__(256) gemv_kernel(
        const float* __restrict__ W, const float* __restrict__ x, float* __restrict__ y,
        const float* __restrict__ aux,
        const float* __restrict__ w1, float* __restrict__ h,
        const float* __restrict__ w2, float* __restrict__ hn,
        const float* __restrict__ scp, float* __restrict__ out2,
        unsigned* __restrict__ cnt) {
    __shared__ float4 sx4[COLS / 4];
    const float4* x4 = (const float4*)x;
    for (int i = threadIdx.x; i < COLS / 4; i += 256) {
        if (GATE) {
            float4 gg = x4[i];
            float4 uu = x4[i + COLS / 4];
            sx4[i] = make_float4(gelu_tanh(gg.x) * uu.x, gelu_tanh(gg.y) * uu.y,
                                 gelu_tanh(gg.z) * uu.z, gelu_tanh(gg.w) * uu.w);
        } else {
            sx4[i] = x4[i];
        }
    }
    __syncthreads();
    int row = blockIdx.x * 8 + (threadIdx.x >> 5);
    int lane = threadIdx.x & 31;
    const float4* Wr = (const float4*)(W + (size_t)row * COLS);
    float acc = 0.f;
#pragma unroll 8
    for (int i = lane; i < COLS / 4; i += 32) {
        float4 w = Wr[i]; float4 v = sx4[i];
        acc = fmaf(w.x, v.x, acc); acc = fmaf(w.y, v.y, acc);
        acc = fmaf(w.z, v.z, acc); acc = fmaf(w.w, v.w, acc);
    }
    acc = warp_sum(acc);
    if (lane == 0) {
        if (MODE == 1) acc = gelu_tanh(acc) * aux[row];
        y[row] = acc;
    }
    if (MODE < 2) return;

    if (!last_block_ticket(cnt, gridDim.x)) return;

    __shared__ float red[256];
    int t = threadIdx.x;
    float vv[8], hv[8]; float ss = 0.f;
#pragma unroll
    for (int j = 0; j < 8; j++) { int i = t + j * 256; vv[j] = y[i]; ss += vv[j] * vv[j]; }
    ss = block_sum_256(ss, red);
    float r1 = rsqrtf(ss / (float)DD + EPSF);
    float sc = (MODE == 3) ? scp[0] : 1.f;
    float ss2 = 0.f;
#pragma unroll
    for (int j = 0; j < 8; j++) {
        int i = t + j * 256;
        float nh = h[i] + vv[j] * r1 * w1[i];
        if (MODE == 3) nh *= sc;
        hv[j] = nh;
        h[i] = nh;
        if (MODE == 3 && out2) out2[i] = nh;
        ss2 += nh * nh;
    }
    if (w2) {
        ss2 = block_sum_256(ss2, red);
        float r2 = rsqrtf(ss2 / (float)DD + EPSF);
#pragma unroll
        for (int j = 0; j < 8; j++) { int i = t + j * 256; hn[i] = hv[j] * r2 * w2[i]; }
    }
}

// ==================================================================================
extern "C" void kernel_launch(void* const* d_in, const int* in_sizes, int n_in,
                              void* d_out, int out_size) {
    const float* hidden = (const float*)d_in[0];
    const float* pls    = (const float*)d_in[3];
    const float* cos_s  = (const float*)d_in[4];
    const float* sin_s  = (const float*)d_in[5];
    const float* cos_f  = (const float*)d_in[6];
    const float* sin_f  = (const float*)d_in[7];
    const float* K_in   = (const float*)d_in[8];
    const float* V_in   = (const float*)d_in[9];
    const float* Wq     = (const float*)d_in[10];
    const float* Wk     = (const float*)d_in[11];
    const float* Wv     = (const float*)d_in[12];
    const float* Wo     = (const float*)d_in[13];
    const float* qn     = (const float*)d_in[14];
    const float* kn     = (const float*)d_in[15];
    const float* ln_in  = (const float*)d_in[16];
    const float* ln_pa  = (const float*)d_in[17];
    const float* ln_pre = (const float*)d_in[18];
    const float* ln_post= (const float*)d_in[19];
    const float* ln_pl  = (const float*)d_in[20];
    const float* Wg     = (const float*)d_in[21];
    const float* Wu     = (const float*)d_in[22];
    const float* Wd     = (const float*)d_in[23];
    const float* Wplg   = (const float*)d_in[24];
    const float* Wplp   = (const float*)d_in[25];
    const float* lsc    = (const float*)d_in[26];

    float* out  = (float*)d_out;
    float* outK = out + DD;
    float* outV = outK + (size_t)LL * KVH * SS * HDIM;

    float *h_, *hn_, *qkv_, *q_, *knew_, *vnew_, *attn_, *ff2_, *vec_, *pl_, *part_;
    unsigned* cnt_;
    cudaGetSymbolAddress((void**)&h_,    g_h);
    cudaGetSymbolAddress((void**)&hn_,   g_hn);
    cudaGetSymbolAddress((void**)&qkv_,  g_qkv);
    cudaGetSymbolAddress((void**)&q_,    g_q);
    cudaGetSymbolAddress((void**)&knew_, g_knew);
    cudaGetSymbolAddress((void**)&vnew_, g_vnew);
    cudaGetSymbolAddress((void**)&attn_, g_attn);
    cudaGetSymbolAddress((void**)&ff2_,  g_ff2);
    cudaGetSymbolAddress((void**)&vec_,  g_vec);
    cudaGetSymbolAddress((void**)&pl_,   g_pl);
    cudaGetSymbolAddress((void**)&part_, g_part);
    cudaGetSymbolAddress((void**)&cnt_,  g_cnt);

    static cudaStream_t side = nullptr;
    static cudaEvent_t evFork = nullptr, evJoin = nullptr;
    if (!side) {
        cudaStreamCreateWithFlags(&side, cudaStreamNonBlocking);
        cudaEventCreateWithFlags(&evFork, cudaEventDisableTiming);
        cudaEventCreateWithFlags(&evJoin, cudaEventDisableTiming);
    }

    // fork: KV bulk copy overlaps the entire layer loop
    cudaEventRecord(evFork, 0);
    cudaStreamWaitEvent(side, evFork, 0);
    const int kvN4 = LL * KVH * SS * HDIM / 4;
    copy_kv_kernel<<<4096, 256, 0, side>>>((const float4*)K_in, (const float4*)V_in,
                                           (float4*)outK, (float4*)outV, kvN4);
    cudaEventRecord(evJoin, side);

    norm0_kernel<<<1, 256>>>(hidden, ln_in, h_, hn_);

    for (int l = 0; l < LL; l++) {
        const float* cosp = (l == 4) ? cos_f : cos_s;   // is_full only layer 4 (L=8)
        const float* sinp = (l == 4) ? sin_f : sin_s;

        const float* Wq_l   = Wq   + (size_t)l * HH * HDIM * DD;
        const float* Wk_l   = Wk   + (size_t)l * KVH * HDIM * DD;
        const float* Wv_l   = Wv   + (size_t)l * KVH * HDIM * DD;
        const float* Wo_l   = Wo   + (size_t)l * DD * HH * HDIM;
        const float* Wg_l   = Wg   + (size_t)l * FFD * DD;
        const float* Wu_l   = Wu   + (size_t)l * FFD * DD;
        const float* Wd_l   = Wd   + (size_t)l * DD * FFD;
        const float* Wplg_l = Wplg + (size_t)l * PLD * DD;
        const float* Wplp_l = Wplp + (size_t)l * DD * PLD;

        const float* Kin_l = K_in + (size_t)l * KVH * SS * HDIM;
        const float* Vin_l = V_in + (size_t)l * KVH * SS * HDIM;
        float* Kpos = outK + (size_t)l * KVH * SS * HDIM + (size_t)POSI * HDIM;
        float* Vpos = outV + (size_t)l * KVH * SS * HDIM + (size_t)POSI * HDIM;

        // attention block
        gemv_qkv_kernel<<<384, 256>>>(Wq_l, Wk_l, Wv_l, hn_, qkv_,
                                      qn + l * HDIM, kn + l * HDIM, cosp, sinp,
                                      q_, knew_, vnew_, Kpos, Vpos, cnt_ + 0);
        attn_part_kernel<<<KVH * NSPL, 256>>>(q_, Kin_l, Vin_l, knew_, vnew_, part_, attn_);
        gemv_kernel<DD, 2, 0><<<256, 256>>>(Wo_l, attn_, vec_, nullptr,
                                            ln_pa + l * DD, h_, ln_pre + l * DD, hn_,
                                            nullptr, nullptr, cnt_ + 1);
        // MLP block: single-stream Wg+Wu GEMV, then Wd with gate folded into staging
        gemv_wgwu_kernel<<<2048, 256>>>(Wg_l, Wu_l, hn_, ff2_);
        gemv_kernel<FFD, 2, 1><<<256, 256>>>(Wd_l, ff2_, vec_, nullptr,
                                             ln_post + l * DD, h_, nullptr, nullptr,
                                             nullptr, nullptr, cnt_ + 2);
        // per-layer embedding block (uses h directly)
        gemv_kernel<DD, 1, 0><<<32, 256>>>(Wplg_l, h_, pl_, pls + l * PLD,
                                           nullptr, nullptr, nullptr, nullptr,
                                           nullptr, nullptr, nullptr);
        gemv_kernel<PLD, 3, 0><<<256, 256>>>(Wplp_l, pl_, vec_, nullptr,
                                             ln_pl + l * DD, h_,
                                             (l < LL - 1) ? (ln_in + (l + 1) * DD) : nullptr, hn_,
                                             lsc + l, (l == LL - 1) ? out : nullptr, cnt_ + 3);
    }

    cudaStreamWaitEvent(0, evJoin, 0);
}